// round 14
// baseline (speedup 1.0000x reference)
#include <cuda_runtime.h>
#include <cuda_fp16.h>
#include <cstdint>

#define BB 4
#define CD 512
#define TD 4096

// ---------------------------------------------------------------------------
// Device scratch (fp16 operands everywhere; fp32 rowsums)
// ---------------------------------------------------------------------------
__device__ __half g_xT[(size_t)BB * TD * CD];   // x transposed: [B][T][C]
__device__ __half g_q [(size_t)BB * TD * CD];   // [B][T][C]  (pre-scaled by 1/sqrt(C))
__device__ __half g_k [(size_t)BB * TD * CD];   // [B][T][C]
__device__ __half g_vT[(size_t)BB * TD * CD];   // [B][C][T]
__device__ __half g_h [(size_t)BB * TD * CD];   // [B][T][C]
__device__ __half g_s [(size_t)BB * TD * TD];   // [B][T][T] unnorm probs (fp16)
__device__ __half g_W [(size_t)4 * CD * CD];    // Wq,Wk,Wv,Wp in fp16
__device__ float  g_prs[(size_t)BB * TD * 32];  // per-block partial row sums
__device__ float  g_rs[(size_t)BB * TD];        // row sums of exp

// ---------------------------------------------------------------------------
// Helpers (base sm_103 target: mma.sync + cp.async + ldmatrix, no tcgen05)
// ---------------------------------------------------------------------------
__device__ __forceinline__ uint32_t smem_u32(const void* p) {
    uint32_t a;
    asm("{ .reg .u64 t; cvta.to.shared.u64 t, %1; cvt.u32.u64 %0, t; }"
        : "=r"(a) : "l"(p));
    return a;
}

__device__ __forceinline__ void cpa16(uint32_t dst, const void* src) {
    asm volatile("cp.async.cg.shared.global [%0], [%1], 16;"
                 :: "r"(dst), "l"(src));
}
#define CP_COMMIT() asm volatile("cp.async.commit_group;" ::: "memory")
#define CP_WAIT(N)  asm volatile("cp.async.wait_group %0;" :: "n"(N) : "memory")

#define LDSM4(r0, r1, r2, r3, addr) \
    asm volatile("ldmatrix.sync.aligned.m8n8.x4.shared.b16 {%0,%1,%2,%3}, [%4];" \
                 : "=r"(r0), "=r"(r1), "=r"(r2), "=r"(r3) : "r"(addr))

// D += A(16x16) * B^T(8x16), fp16 in, fp32 accum
__device__ __forceinline__ void mma16(float* c, const uint32_t* a, const uint32_t* b) {
    asm volatile(
        "mma.sync.aligned.m16n8k16.row.col.f32.f16.f16.f32 "
        "{%0,%1,%2,%3}, {%4,%5,%6,%7}, {%8,%9}, {%0,%1,%2,%3};"
        : "+f"(c[0]), "+f"(c[1]), "+f"(c[2]), "+f"(c[3])
        : "r"(a[0]), "r"(a[1]), "r"(a[2]), "r"(a[3]),
          "r"(b[0]), "r"(b[1]));
}

// D += A(16x16) * B^T(8x16), fp16 in, fp16 accum (2 packed regs)
__device__ __forceinline__ void mma16h(uint32_t* c, const uint32_t* a, const uint32_t* b) {
    asm volatile(
        "mma.sync.aligned.m16n8k16.row.col.f16.f16.f16.f16 "
        "{%0,%1}, {%2,%3,%4,%5}, {%6,%7}, {%0,%1};"
        : "+r"(c[0]), "+r"(c[1])
        : "r"(a[0]), "r"(a[1]), "r"(a[2]), "r"(a[3]),
          "r"(b[0]), "r"(b[1]));
}

// ---------------------------------------------------------------------------
// Tile config: 128x128 CTA tile, 8 warps, 64x32 warp tile, fp16, BK=64
// ---------------------------------------------------------------------------
#define BM 128
#define BN 128
#define BK 64            // halfs per stage
#define PAD 72           // row pitch in halfs (144B = 9 granules -> LDSM conflict-free)
#define NSTAGE 3
#define NTHR 256
#define ATT_SCALE 0.044194173824159216f  // 1/sqrt(512)

#define BUF_HALFS  (BM * PAD)                  // 9216 halfs = 18432 B
#define BUF_STRIDE (BUF_HALFS * 2)             // bytes
#define SMEM_BYTES (2 * NSTAGE * BUF_STRIDE)   // 110592 (x2 CTAs = 221184 <= 228KB)

// MODE: 0 = D=(A.B^T + bias[n]) * oscale  (q & k fused; q gets oscale=1/sqrt(C))
//       1 = D=A.B^T + bias[m]                 -> half   (v proj, transposed out)
//       2 = D=A.B^T + bias[m] + resid         -> float  (out projection)
//       3 = D=exp(A.B^T) causal-masked (fp16 acc) -> half + partial row sums
//       4 = D=(A.B^T)/rowsum[m], K=(mb+1)*BM  -> half   (PV, normalize)
template <int MODE>
__global__ __launch_bounds__(NTHR, 2) void gemm_mma(
    const __half* __restrict__ A, const __half* __restrict__ B, void* __restrict__ Dv,
    const float* __restrict__ bias, const float* __restrict__ resid,
    long lda, long ldb, long ldd, long sA, long sB, long sD, int Kparam,
    const __half* B2, void* Dv2, const float* bias2)
{
    const int nb = blockIdx.x;
    int bz = blockIdx.z;
    float oscale = 1.0f;
    if (MODE == 0) {
        if (bz & 1) { B = B2; Dv = Dv2; bias = bias2; }
        else        { oscale = ATT_SCALE; }   // q path: fold in attention scale
        bz >>= 1;
    }
    const int mb = (MODE == 3 || MODE == 4) ? (gridDim.y - 1 - blockIdx.y)
                                            : blockIdx.y;
    if (MODE == 3 && nb > mb) return;   // causal tile skip

    const int n0 = nb * BN, m0 = mb * BM;
    const int K = (MODE == 4) ? (mb + 1) * BM : Kparam;
    const int nst = K / BK;

    A += (size_t)bz * sA;
    B += (size_t)bz * sB;
    __half* Dh = (MODE == 2) ? nullptr : ((__half*)Dv + (size_t)bz * sD);
    float*  Df = (MODE == 2) ? ((float*)Dv + (size_t)bz * sD) : nullptr;
    const float* R  = (MODE == 2) ? (resid + (size_t)bz * sD) : nullptr;
    const float* RS = (MODE == 4) ? (bias + (size_t)bz * TD) : nullptr;

    extern __shared__ __half sm[];
    __half* AsBase = sm;
    __half* BsBase = sm + NSTAGE * BUF_HALFS;

    const int tid  = threadIdx.x;
    const int wid  = tid >> 5;
    const int lane = tid & 31;
    const int g    = lane >> 2;
    const int tg   = lane & 3;
    const int wm   = (wid >> 2) * 64;
    const int wn   = (wid & 3) * 32;

    const int ldr = tid >> 3;          // load row (0..31 per round)
    const int ldq = tid & 7;           // 16B chunk (8 halfs) in row

    // ---- ldmatrix per-lane byte offsets -----------------------------------
    const int lr = lane & 7;
    const int lt = lane >> 3;
    const uint32_t uAs = smem_u32(AsBase);
    const uint32_t uBs = smem_u32(BsBase);

    uint32_t aOff[4], bOff[2];
    #pragma unroll
    for (int mt = 0; mt < 4; mt++) {
        int row = wm + mt * 16 + (lt & 1) * 8 + lr;
        int col = (lt >> 1) * 8;
        aOff[mt] = (uint32_t)(row * PAD + col) * 2u;
    }
    #pragma unroll
    for (int p = 0; p < 2; p++) {
        int row = wn + p * 16 + (lt >> 1) * 8 + lr;
        int col = (lt & 1) * 8;
        bOff[p] = (uint32_t)(row * PAD + col) * 2u;
    }

    float    acc [4][4][4] = {};     // fp32 accum (modes != 3)
    uint32_t acch[4][4][2] = {};     // fp16 accum (mode 3)

    // ---- prologue: prefetch stages 0 and 1 --------------------------------
    #pragma unroll
    for (int p = 0; p < 2; p++) {
        const int k0 = p * BK;
        #pragma unroll
        for (int i = 0; i < 4; i++) {
            int r = ldr + i * 32;
            cpa16(smem_u32(AsBase + p * BUF_HALFS + r * PAD + ldq * 8),
                  A + (size_t)(m0 + r) * lda + k0 + ldq * 8);
            cpa16(smem_u32(BsBase + p * BUF_HALFS + r * PAD + ldq * 8),
                  B + (size_t)(n0 + r) * ldb + k0 + ldq * 8);
        }
        CP_COMMIT();
    }

    int buf = 0, nbuf = 2;
    for (int st = 0; st < nst; st++) {
        if (st < nst - 1) { CP_WAIT(1); } else { CP_WAIT(0); }
        __syncthreads();

        if (st + 2 < nst) {
            const int k0 = (st + 2) * BK;
            #pragma unroll
            for (int i = 0; i < 4; i++) {
                int r = ldr + i * 32;
                cpa16(smem_u32(AsBase + nbuf * BUF_HALFS + r * PAD + ldq * 8),
                      A + (size_t)(m0 + r) * lda + k0 + ldq * 8);
                cpa16(smem_u32(BsBase + nbuf * BUF_HALFS + r * PAD + ldq * 8),
                      B + (size_t)(n0 + r) * ldb + k0 + ldq * 8);
            }
            CP_COMMIT();
        }

        const uint32_t aBase = uAs + (uint32_t)buf * BUF_STRIDE;
        const uint32_t bBase = uBs + (uint32_t)buf * BUF_STRIDE;

        #pragma unroll
        for (int k16 = 0; k16 < BK / 16; k16++) {
            const uint32_t kByte = (uint32_t)k16 * 32u;   // 16 halfs
            uint32_t af[4][4], bf[4][2];
            #pragma unroll
            for (int mt = 0; mt < 4; mt++)
                LDSM4(af[mt][0], af[mt][1], af[mt][2], af[mt][3],
                      aBase + aOff[mt] + kByte);
            LDSM4(bf[0][0], bf[0][1], bf[1][0], bf[1][1], bBase + bOff[0] + kByte);
            LDSM4(bf[2][0], bf[2][1], bf[3][0], bf[3][1], bBase + bOff[1] + kByte);

            #pragma unroll
            for (int mt = 0; mt < 4; mt++)
                #pragma unroll
                for (int nt = 0; nt < 4; nt++) {
                    if (MODE == 3) mma16h(acch[mt][nt], af[mt], bf[nt]);
                    else           mma16 (acc [mt][nt], af[mt], bf[nt]);
                }
        }

        buf  = (buf  == NSTAGE - 1) ? 0 : buf + 1;
        nbuf = (nbuf == NSTAGE - 1) ? 0 : nbuf + 1;
    }

    // ---- epilogue ----------------------------------------------------------
    const bool diag = (MODE == 3) && (nb == mb);
    float* prsm = (float*)sm;   // reuse operand smem: [128 rows][4 n-warps]
    if (MODE == 3) __syncthreads();   // all warps done reading operand smem

    #pragma unroll
    for (int mt = 0; mt < 4; mt++) {
        const int r0 = m0 + wm + mt * 16 + g;
        const int r1 = r0 + 8;
        float bm0 = 0.f, bm1 = 0.f;
        if (MODE == 1 || MODE == 2) { bm0 = bias[r0]; bm1 = bias[r1]; }
        float ri0 = 1.f, ri1 = 1.f;
        if (MODE == 4) { ri0 = 1.0f / RS[r0]; ri1 = 1.0f / RS[r1]; }
        float rs0 = 0.f, rs1 = 0.f;
        #pragma unroll
        for (int nt = 0; nt < 4; nt++) {
            const int cc = n0 + wn + nt * 8 + tg * 2;
            float v00, v01, v10, v11;
            if (MODE == 3) {
                float2 lo = __half22float2(*(__half2*)&acch[mt][nt][0]);
                float2 hi = __half22float2(*(__half2*)&acch[mt][nt][1]);
                v00 = lo.x; v01 = lo.y; v10 = hi.x; v11 = hi.y;
            } else {
                v00 = acc[mt][nt][0]; v01 = acc[mt][nt][1];
                v10 = acc[mt][nt][2]; v11 = acc[mt][nt][3];
            }
            if (MODE == 0) {
                float b0 = bias[cc], b1 = bias[cc + 1];
                v00 = (v00 + b0) * oscale; v01 = (v01 + b1) * oscale;
                v10 = (v10 + b0) * oscale; v11 = (v11 + b1) * oscale;
            }
            if (MODE == 1 || MODE == 2) {
                v00 += bm0; v01 += bm0; v10 += bm1; v11 += bm1;
            }
            if (MODE == 3) {
                v00 = __expf(v00);
                v01 = __expf(v01);
                v10 = __expf(v10);
                v11 = __expf(v11);
                if (diag) {
                    if (cc     > r0) v00 = 0.f;
                    if (cc + 1 > r0) v01 = 0.f;
                    if (cc     > r1) v10 = 0.f;
                    if (cc + 1 > r1) v11 = 0.f;
                }
                rs0 += v00 + v01;
                rs1 += v10 + v11;
            }
            if (MODE == 4) {
                v00 *= ri0; v01 *= ri0; v10 *= ri1; v11 *= ri1;
            }
            if (MODE == 2) {
                float2 x0 = *(const float2*)(R + (size_t)r0 * ldd + cc);
                float2 x1 = *(const float2*)(R + (size_t)r1 * ldd + cc);
                *(float2*)(Df + (size_t)r0 * ldd + cc) = make_float2(v00 + x0.x, v01 + x0.y);
                *(float2*)(Df + (size_t)r1 * ldd + cc) = make_float2(v10 + x1.x, v11 + x1.y);
            } else {
                *(__half2*)(Dh + (size_t)r0 * ldd + cc) = __floats2half2_rn(v00, v01);
                *(__half2*)(Dh + (size_t)r1 * ldd + cc) = __floats2half2_rn(v10, v11);
            }
        }
        if (MODE == 3) {
            rs0 += __shfl_xor_sync(0xffffffffu, rs0, 1);
            rs0 += __shfl_xor_sync(0xffffffffu, rs0, 2);
            rs1 += __shfl_xor_sync(0xffffffffu, rs1, 1);
            rs1 += __shfl_xor_sync(0xffffffffu, rs1, 2);
            if (tg == 0) {
                prsm[(wm + mt * 16 + g)     * 4 + (wid & 3)] = rs0;
                prsm[(wm + mt * 16 + g + 8) * 4 + (wid & 3)] = rs1;
            }
        }
    }

    if (MODE == 3) {
        __syncthreads();
        if (tid < 128) {
            const float* pr = prsm + tid * 4;
            g_prs[((size_t)bz * TD + m0 + tid) * 32 + nb] =
                (pr[0] + pr[1]) + (pr[2] + pr[3]);
        }
    }
}

// ---------------------------------------------------------------------------
// Weight conversion: 4 x [CD*CD] fp32 -> fp16
// ---------------------------------------------------------------------------
__global__ __launch_bounds__(256) void k_cvt_w(
    const float* __restrict__ W0, const float* __restrict__ W1,
    const float* __restrict__ W2, const float* __restrict__ W3)
{
    const int idx = blockIdx.x * 256 + threadIdx.x;
    const float* src[4] = {W0, W1, W2, W3};
    #pragma unroll
    for (int w = 0; w < 4; w++)
        g_W[(size_t)w * CD * CD + idx] = __float2half_rn(src[w][idx]);
}

// ---------------------------------------------------------------------------
// Transpose + convert: x[b,c,t] fp32 -> xT[b,t,c] fp16
// ---------------------------------------------------------------------------
__global__ __launch_bounds__(256) void k_transpose(const float* __restrict__ x)
{
    __shared__ float tile[32][33];
    const int b  = blockIdx.z;
    const int t0 = blockIdx.x * 32;
    const int c0 = blockIdx.y * 32;
    const int tx = threadIdx.x, ty = threadIdx.y;

    #pragma unroll
    for (int i = ty; i < 32; i += 8)
        tile[i][tx] = x[((size_t)b * CD + c0 + i) * TD + t0 + tx];
    __syncthreads();
    #pragma unroll
    for (int i = ty; i < 32; i += 8)
        g_xT[((size_t)b * TD + t0 + i) * CD + c0 + tx] = __float2half_rn(tile[tx][i]);
}

// ---------------------------------------------------------------------------
// Final row-sum reduce: g_rs[b][t] = sum over valid nb of g_prs[b][t][nb]
// ---------------------------------------------------------------------------
__global__ __launch_bounds__(256) void k_rsreduce()
{
    const int idx = blockIdx.x * 256 + threadIdx.x;   // b*TD + t
    const int t = idx & (TD - 1);
    const int nmax = t >> 7;                           // last valid tile col
    const float* p = g_prs + (size_t)idx * 32;
    float s = 0.f;
    for (int i = 0; i <= nmax; i++) s += p[i];
    g_rs[idx] = s;
}

// ---------------------------------------------------------------------------
extern "C" void kernel_launch(void* const* d_in, const int* in_sizes, int n_in,
                              void* d_out, int out_size)
{
    const float* x  = (const float*)d_in[0];
    const float* Wq = (const float*)d_in[1];
    const float* bq = (const float*)d_in[2];
    const float* Wk = (const float*)d_in[3];
    const float* bk = (const float*)d_in[4];
    const float* Wv = (const float*)d_in[5];
    const float* bv = (const float*)d_in[6];
    const float* Wp = (const float*)d_in[7];
    const float* bp = (const float*)d_in[8];
    float* out = (float*)d_out;

    __half *xT, *q, *k, *vT, *h, *s, *W;
    float *rs;
    cudaGetSymbolAddress((void**)&xT, g_xT);
    cudaGetSymbolAddress((void**)&q,  g_q);
    cudaGetSymbolAddress((void**)&k,  g_k);
    cudaGetSymbolAddress((void**)&vT, g_vT);
    cudaGetSymbolAddress((void**)&h,  g_h);
    cudaGetSymbolAddress((void**)&s,  g_s);
    cudaGetSymbolAddress((void**)&W,  g_W);
    cudaGetSymbolAddress((void**)&rs, g_rs);

    const long TC = (long)TD * CD;
    const long SS = (long)TD * TD;
    const long WW = (long)CD * CD;

    cudaFuncSetAttribute(gemm_mma<0>, cudaFuncAttributeMaxDynamicSharedMemorySize, SMEM_BYTES);
    cudaFuncSetAttribute(gemm_mma<1>, cudaFuncAttributeMaxDynamicSharedMemorySize, SMEM_BYTES);
    cudaFuncSetAttribute(gemm_mma<2>, cudaFuncAttributeMaxDynamicSharedMemorySize, SMEM_BYTES);
    cudaFuncSetAttribute(gemm_mma<3>, cudaFuncAttributeMaxDynamicSharedMemorySize, SMEM_BYTES);
    cudaFuncSetAttribute(gemm_mma<4>, cudaFuncAttributeMaxDynamicSharedMemorySize, SMEM_BYTES);

    // 0) convert weights to fp16; transpose+convert x
    k_cvt_w<<<(CD * CD) / 256, 256>>>(Wq, Wk, Wv, Wp);
    k_transpose<<<dim3(TD / 32, CD / 32, BB), dim3(32, 8)>>>(x);

    // 1) fused q & k projections (z: batch*2, odd -> k); q pre-scaled
    gemm_mma<0><<<dim3(CD / BN, TD / BM, BB * 2), NTHR, SMEM_BYTES>>>(
        xT, W + 0 * WW, q, bq, nullptr, CD, CD, CD, TC, 0, TC, CD,
        W + 1 * WW, k, bk);

    // 2) vT = Wv.xT^T + bv  -> [C][T]
    gemm_mma<1><<<dim3(TD / BN, CD / BM, BB), NTHR, SMEM_BYTES>>>(
        W + 2 * WW, xT, vT, bv, nullptr, CD, CD, TD, 0, TC, TC, CD,
        nullptr, nullptr, nullptr);

    // 3) P = exp(q.k^T) (scale pre-folded), causal-masked, fp16 acc
    gemm_mma<3><<<dim3(TD / BN, TD / BM, BB), NTHR, SMEM_BYTES>>>(
        q, k, s, nullptr, nullptr, CD, CD, TD, TC, TC, SS, CD,
        nullptr, nullptr, nullptr);

    // 4) tiny reduce of partial sums (<=32 per row)
    k_rsreduce<<<(BB * TD) / 256, 256>>>();

    // 5) h = (P.vT^T)/rowsum, fp16 operands, fp32 accum
    gemm_mma<4><<<dim3(CD / BN, TD / BM, BB), NTHR, SMEM_BYTES>>>(
        s, vT, h, rs, nullptr, TD, TD, CD, SS, TC, TC, 0,
        nullptr, nullptr, nullptr);

    // 6) out = Wp.h^T + bp + x  (fp32 out)
    gemm_mma<2><<<dim3(TD / BN, CD / BM, BB), NTHR, SMEM_BYTES>>>(
        W + 3 * WW, h, out, bp, x, CD, CD, TD, 0, TC, TC, CD,
        nullptr, nullptr, nullptr);
}

// round 15
// speedup vs baseline: 1.0140x; 1.0140x over previous
#include <cuda_runtime.h>
#include <cuda_fp16.h>
#include <cstdint>

#define BB 4
#define CD 512
#define TD 4096

// ---------------------------------------------------------------------------
// Device scratch (fp16 operands everywhere; fp32 rowsums)
// ---------------------------------------------------------------------------
__device__ __half g_xT[(size_t)BB * TD * CD];   // x transposed: [B][T][C]
__device__ __half g_q [(size_t)BB * TD * CD];   // [B][T][C]
__device__ __half g_k [(size_t)BB * TD * CD];   // [B][T][C]
__device__ __half g_vT[(size_t)BB * TD * CD];   // [B][C][T]
__device__ __half g_h [(size_t)BB * TD * CD];   // [B][T][C]
__device__ __half g_s [(size_t)BB * TD * TD];   // [B][T][T] unnorm probs (fp16)
__device__ __half g_W [(size_t)4 * CD * CD];    // Wq,Wk,Wv,Wp in fp16
__device__ float  g_prs[(size_t)BB * TD * 32];  // per-block partial row sums
__device__ float  g_rs[(size_t)BB * TD];        // row sums of exp

// ---------------------------------------------------------------------------
// Helpers (base sm_103 target: mma.sync + cp.async + ldmatrix, no tcgen05)
// ---------------------------------------------------------------------------
__device__ __forceinline__ uint32_t smem_u32(const void* p) {
    uint32_t a;
    asm("{ .reg .u64 t; cvta.to.shared.u64 t, %1; cvt.u32.u64 %0, t; }"
        : "=r"(a) : "l"(p));
    return a;
}

__device__ __forceinline__ void cpa16(uint32_t dst, const void* src) {
    asm volatile("cp.async.cg.shared.global [%0], [%1], 16;"
                 :: "r"(dst), "l"(src));
}
#define CP_COMMIT() asm volatile("cp.async.commit_group;" ::: "memory")
#define CP_WAIT(N)  asm volatile("cp.async.wait_group %0;" :: "n"(N) : "memory")

#define LDSM4(r0, r1, r2, r3, addr) \
    asm volatile("ldmatrix.sync.aligned.m8n8.x4.shared.b16 {%0,%1,%2,%3}, [%4];" \
                 : "=r"(r0), "=r"(r1), "=r"(r2), "=r"(r3) : "r"(addr))

// D += A(16x16) * B^T(8x16), fp16 in, fp32 accum
__device__ __forceinline__ void mma16(float* c, const uint32_t* a, const uint32_t* b) {
    asm volatile(
        "mma.sync.aligned.m16n8k16.row.col.f32.f16.f16.f32 "
        "{%0,%1,%2,%3}, {%4,%5,%6,%7}, {%8,%9}, {%0,%1,%2,%3};"
        : "+f"(c[0]), "+f"(c[1]), "+f"(c[2]), "+f"(c[3])
        : "r"(a[0]), "r"(a[1]), "r"(a[2]), "r"(a[3]),
          "r"(b[0]), "r"(b[1]));
}

// ---------------------------------------------------------------------------
// Tile config: 128x128 CTA tile, 8 warps, 64x32 warp tile, fp16, BK=64
// (= round-13 configuration, the measured optimum)
// ---------------------------------------------------------------------------
#define BM 128
#define BN 128
#define BK 64            // halfs per stage
#define PAD 72           // row pitch in halfs (144B = 9 granules -> LDSM conflict-free)
#define NSTAGE 3
#define NTHR 256
#define ATT_SCALE 0.044194173824159216f  // 1/sqrt(512)

#define BUF_HALFS  (BM * PAD)                  // 9216 halfs = 18432 B
#define BUF_STRIDE (BUF_HALFS * 2)             // bytes
#define SMEM_BYTES (2 * NSTAGE * BUF_STRIDE)   // 110592 (x2 CTAs = 221184 <= 228KB)

// MODE: 0 = D=A.B^T + bias[n]  (q & k projections fused: z&1 selects)
//       1 = D=A.B^T + bias[m]                 -> half   (v proj, transposed out)
//       2 = D=A.B^T + bias[m] + resid         -> float  (out projection)
//       3 = D=exp(A.B^T*scale) causal-masked  -> half   + partial row sums
//       4 = D=(A.B^T)/rowsum[m], K=(mb+1)*BM  -> half   (PV, normalize)
template <int MODE>
__global__ __launch_bounds__(NTHR, 2) void gemm_mma(
    const __half* __restrict__ A, const __half* __restrict__ B, void* __restrict__ Dv,
    const float* __restrict__ bias, const float* __restrict__ resid,
    long lda, long ldb, long ldd, long sA, long sB, long sD, int Kparam,
    const __half* B2, void* Dv2, const float* bias2)
{
    const int nb = blockIdx.x;
    int bz = blockIdx.z;
    if (MODE == 0) {
        if (bz & 1) { B = B2; Dv = Dv2; bias = bias2; }
        bz >>= 1;
    }
    const int mb = (MODE == 3 || MODE == 4) ? (gridDim.y - 1 - blockIdx.y)
                                            : blockIdx.y;
    if (MODE == 3 && nb > mb) return;   // causal tile skip

    const int n0 = nb * BN, m0 = mb * BM;
    const int K = (MODE == 4) ? (mb + 1) * BM : Kparam;
    const int nst = K / BK;

    A += (size_t)bz * sA;
    B += (size_t)bz * sB;
    __half* Dh = (MODE == 2) ? nullptr : ((__half*)Dv + (size_t)bz * sD);
    float*  Df = (MODE == 2) ? ((float*)Dv + (size_t)bz * sD) : nullptr;
    const float* R  = (MODE == 2) ? (resid + (size_t)bz * sD) : nullptr;
    const float* RS = (MODE == 4) ? (bias + (size_t)bz * TD) : nullptr;

    extern __shared__ __half sm[];
    __half* AsBase = sm;
    __half* BsBase = sm + NSTAGE * BUF_HALFS;

    const int tid  = threadIdx.x;
    const int wid  = tid >> 5;
    const int lane = tid & 31;
    const int g    = lane >> 2;
    const int tg   = lane & 3;
    const int wm   = (wid >> 2) * 64;
    const int wn   = (wid & 3) * 32;

    const int ldr = tid >> 3;          // load row (0..31 per round)
    const int ldq = tid & 7;           // 16B chunk (8 halfs) in row

    // ---- ldmatrix per-lane byte offsets -----------------------------------
    const int lr = lane & 7;
    const int lt = lane >> 3;
    const uint32_t uAs = smem_u32(AsBase);
    const uint32_t uBs = smem_u32(BsBase);

    uint32_t aOff[4], bOff[2];
    #pragma unroll
    for (int mt = 0; mt < 4; mt++) {
        int row = wm + mt * 16 + (lt & 1) * 8 + lr;
        int col = (lt >> 1) * 8;
        aOff[mt] = (uint32_t)(row * PAD + col) * 2u;
    }
    #pragma unroll
    for (int p = 0; p < 2; p++) {
        int row = wn + p * 16 + (lt >> 1) * 8 + lr;
        int col = (lt & 1) * 8;
        bOff[p] = (uint32_t)(row * PAD + col) * 2u;
    }

    float acc[4][4][4] = {};

    // ---- prologue: prefetch stages 0 and 1 --------------------------------
    #pragma unroll
    for (int p = 0; p < 2; p++) {
        const int k0 = p * BK;
        #pragma unroll
        for (int i = 0; i < 4; i++) {
            int r = ldr + i * 32;
            cpa16(smem_u32(AsBase + p * BUF_HALFS + r * PAD + ldq * 8),
                  A + (size_t)(m0 + r) * lda + k0 + ldq * 8);
            cpa16(smem_u32(BsBase + p * BUF_HALFS + r * PAD + ldq * 8),
                  B + (size_t)(n0 + r) * ldb + k0 + ldq * 8);
        }
        CP_COMMIT();
    }

    int buf = 0, nbuf = 2;
    for (int st = 0; st < nst; st++) {
        if (st < nst - 1) { CP_WAIT(1); } else { CP_WAIT(0); }
        __syncthreads();

        if (st + 2 < nst) {
            const int k0 = (st + 2) * BK;
            #pragma unroll
            for (int i = 0; i < 4; i++) {
                int r = ldr + i * 32;
                cpa16(smem_u32(AsBase + nbuf * BUF_HALFS + r * PAD + ldq * 8),
                      A + (size_t)(m0 + r) * lda + k0 + ldq * 8);
                cpa16(smem_u32(BsBase + nbuf * BUF_HALFS + r * PAD + ldq * 8),
                      B + (size_t)(n0 + r) * ldb + k0 + ldq * 8);
            }
            CP_COMMIT();
        }

        const uint32_t aBase = uAs + (uint32_t)buf * BUF_STRIDE;
        const uint32_t bBase = uBs + (uint32_t)buf * BUF_STRIDE;

        #pragma unroll
        for (int k16 = 0; k16 < BK / 16; k16++) {
            const uint32_t kByte = (uint32_t)k16 * 32u;   // 16 halfs
            uint32_t af[4][4], bf[4][2];
            #pragma unroll
            for (int mt = 0; mt < 4; mt++)
                LDSM4(af[mt][0], af[mt][1], af[mt][2], af[mt][3],
                      aBase + aOff[mt] + kByte);
            LDSM4(bf[0][0], bf[0][1], bf[1][0], bf[1][1], bBase + bOff[0] + kByte);
            LDSM4(bf[2][0], bf[2][1], bf[3][0], bf[3][1], bBase + bOff[1] + kByte);

            #pragma unroll
            for (int mt = 0; mt < 4; mt++)
                #pragma unroll
                for (int nt = 0; nt < 4; nt++)
                    mma16(acc[mt][nt], af[mt], bf[nt]);
        }

        buf  = (buf  == NSTAGE - 1) ? 0 : buf + 1;
        nbuf = (nbuf == NSTAGE - 1) ? 0 : nbuf + 1;
    }

    // ---- epilogue ----------------------------------------------------------
    const bool diag = (MODE == 3) && (nb == mb);
    float* prsm = (float*)sm;   // reuse operand smem: [128 rows][4 n-warps]
    if (MODE == 3) __syncthreads();   // all warps done reading operand smem

    #pragma unroll
    for (int mt = 0; mt < 4; mt++) {
        const int r0 = m0 + wm + mt * 16 + g;
        const int r1 = r0 + 8;
        float bm0 = 0.f, bm1 = 0.f;
        if (MODE == 1 || MODE == 2) { bm0 = bias[r0]; bm1 = bias[r1]; }
        float ri0 = 1.f, ri1 = 1.f;
        if (MODE == 4) { ri0 = 1.0f / RS[r0]; ri1 = 1.0f / RS[r1]; }
        float rs0 = 0.f, rs1 = 0.f;
        #pragma unroll
        for (int nt = 0; nt < 4; nt++) {
            const int cc = n0 + wn + nt * 8 + tg * 2;
            float v00 = acc[mt][nt][0], v01 = acc[mt][nt][1];
            float v10 = acc[mt][nt][2], v11 = acc[mt][nt][3];
            if (MODE == 0) {
                float b0 = bias[cc], b1 = bias[cc + 1];
                v00 += b0; v01 += b1; v10 += b0; v11 += b1;
            }
            if (MODE == 1 || MODE == 2) {
                v00 += bm0; v01 += bm0; v10 += bm1; v11 += bm1;
            }
            if (MODE == 3) {
                v00 = __expf(v00 * ATT_SCALE);
                v01 = __expf(v01 * ATT_SCALE);
                v10 = __expf(v10 * ATT_SCALE);
                v11 = __expf(v11 * ATT_SCALE);
                if (diag) {
                    if (cc     > r0) v00 = 0.f;
                    if (cc + 1 > r0) v01 = 0.f;
                    if (cc     > r1) v10 = 0.f;
                    if (cc + 1 > r1) v11 = 0.f;
                }
                rs0 += v00 + v01;
                rs1 += v10 + v11;
            }
            if (MODE == 4) {
                v00 *= ri0; v01 *= ri0; v10 *= ri1; v11 *= ri1;
            }
            if (MODE == 2) {
                float2 x0 = *(const float2*)(R + (size_t)r0 * ldd + cc);
                float2 x1 = *(const float2*)(R + (size_t)r1 * ldd + cc);
                *(float2*)(Df + (size_t)r0 * ldd + cc) = make_float2(v00 + x0.x, v01 + x0.y);
                *(float2*)(Df + (size_t)r1 * ldd + cc) = make_float2(v10 + x1.x, v11 + x1.y);
            } else {
                *(__half2*)(Dh + (size_t)r0 * ldd + cc) = __floats2half2_rn(v00, v01);
                *(__half2*)(Dh + (size_t)r1 * ldd + cc) = __floats2half2_rn(v10, v11);
            }
        }
        if (MODE == 3) {
            rs0 += __shfl_xor_sync(0xffffffffu, rs0, 1);
            rs0 += __shfl_xor_sync(0xffffffffu, rs0, 2);
            rs1 += __shfl_xor_sync(0xffffffffu, rs1, 1);
            rs1 += __shfl_xor_sync(0xffffffffu, rs1, 2);
            if (tg == 0) {
                prsm[(wm + mt * 16 + g)     * 4 + (wid & 3)] = rs0;
                prsm[(wm + mt * 16 + g + 8) * 4 + (wid & 3)] = rs1;
            }
        }
    }

    if (MODE == 3) {
        __syncthreads();
        if (tid < 128) {
            const float* pr = prsm + tid * 4;
            g_prs[((size_t)bz * TD + m0 + tid) * 32 + nb] =
                (pr[0] + pr[1]) + (pr[2] + pr[3]);
        }
    }
}

// ---------------------------------------------------------------------------
// Weight conversion: 4 x [CD*CD] fp32 -> fp16
// ---------------------------------------------------------------------------
__global__ __launch_bounds__(256) void k_cvt_w(
    const float* __restrict__ W0, const float* __restrict__ W1,
    const float* __restrict__ W2, const float* __restrict__ W3)
{
    const int idx = blockIdx.x * 256 + threadIdx.x;
    const float* src[4] = {W0, W1, W2, W3};
    #pragma unroll
    for (int w = 0; w < 4; w++)
        g_W[(size_t)w * CD * CD + idx] = __float2half_rn(src[w][idx]);
}

// ---------------------------------------------------------------------------
// Transpose + convert: x[b,c,t] fp32 -> xT[b,t,c] fp16
// ---------------------------------------------------------------------------
__global__ __launch_bounds__(256) void k_transpose(const float* __restrict__ x)
{
    __shared__ float tile[32][33];
    const int b  = blockIdx.z;
    const int t0 = blockIdx.x * 32;
    const int c0 = blockIdx.y * 32;
    const int tx = threadIdx.x, ty = threadIdx.y;

    #pragma unroll
    for (int i = ty; i < 32; i += 8)
        tile[i][tx] = x[((size_t)b * CD + c0 + i) * TD + t0 + tx];
    __syncthreads();
    #pragma unroll
    for (int i = ty; i < 32; i += 8)
        g_xT[((size_t)b * TD + t0 + i) * CD + c0 + tx] = __float2half_rn(tile[tx][i]);
}

// ---------------------------------------------------------------------------
// Final row-sum reduce: g_rs[b][t] = sum over valid nb of g_prs[b][t][nb]
// ---------------------------------------------------------------------------
__global__ __launch_bounds__(256) void k_rsreduce()
{
    const int idx = blockIdx.x * 256 + threadIdx.x;   // b*TD + t
    const int t = idx & (TD - 1);
    const int nmax = t >> 7;                           // last valid tile col
    const float* p = g_prs + (size_t)idx * 32;
    float s = 0.f;
    for (int i = 0; i <= nmax; i++) s += p[i];
    g_rs[idx] = s;
}

// ---------------------------------------------------------------------------
extern "C" void kernel_launch(void* const* d_in, const int* in_sizes, int n_in,
                              void* d_out, int out_size)
{
    const float* x  = (const float*)d_in[0];
    const float* Wq = (const float*)d_in[1];
    const float* bq = (const float*)d_in[2];
    const float* Wk = (const float*)d_in[3];
    const float* bk = (const float*)d_in[4];
    const float* Wv = (const float*)d_in[5];
    const float* bv = (const float*)d_in[6];
    const float* Wp = (const float*)d_in[7];
    const float* bp = (const float*)d_in[8];
    float* out = (float*)d_out;

    __half *xT, *q, *k, *vT, *h, *s, *W;
    float *rs;
    cudaGetSymbolAddress((void**)&xT, g_xT);
    cudaGetSymbolAddress((void**)&q,  g_q);
    cudaGetSymbolAddress((void**)&k,  g_k);
    cudaGetSymbolAddress((void**)&vT, g_vT);
    cudaGetSymbolAddress((void**)&h,  g_h);
    cudaGetSymbolAddress((void**)&s,  g_s);
    cudaGetSymbolAddress((void**)&W,  g_W);
    cudaGetSymbolAddress((void**)&rs, g_rs);

    const long TC = (long)TD * CD;
    const long SS = (long)TD * TD;
    const long WW = (long)CD * CD;

    // one-time host-side resources (same topology on every call)
    static cudaStream_t s2 = nullptr;
    static cudaEvent_t evFork = nullptr, evJoin = nullptr;
    static bool attr_done = false;
    if (!attr_done) {
        cudaStreamCreateWithFlags(&s2, cudaStreamNonBlocking);
        cudaEventCreateWithFlags(&evFork, cudaEventDisableTiming);
        cudaEventCreateWithFlags(&evJoin, cudaEventDisableTiming);
        cudaFuncSetAttribute(gemm_mma<0>, cudaFuncAttributeMaxDynamicSharedMemorySize, SMEM_BYTES);
        cudaFuncSetAttribute(gemm_mma<1>, cudaFuncAttributeMaxDynamicSharedMemorySize, SMEM_BYTES);
        cudaFuncSetAttribute(gemm_mma<2>, cudaFuncAttributeMaxDynamicSharedMemorySize, SMEM_BYTES);
        cudaFuncSetAttribute(gemm_mma<3>, cudaFuncAttributeMaxDynamicSharedMemorySize, SMEM_BYTES);
        cudaFuncSetAttribute(gemm_mma<4>, cudaFuncAttributeMaxDynamicSharedMemorySize, SMEM_BYTES);
        attr_done = true;
    }

    // 0) convert weights to fp16; transpose+convert x   (stream 0)
    k_cvt_w<<<(CD * CD) / 256, 256>>>(Wq, Wk, Wv, Wp);
    k_transpose<<<dim3(TD / 32, CD / 32, BB), dim3(32, 8)>>>(x);

    // fork: v projection runs on s2 concurrently with qk-proj + scores
    cudaEventRecord(evFork, 0);
    cudaStreamWaitEvent(s2, evFork, 0);
    gemm_mma<1><<<dim3(TD / BN, CD / BM, BB), NTHR, SMEM_BYTES, s2>>>(
        W + 2 * WW, xT, vT, bv, nullptr, CD, CD, TD, 0, TC, TC, CD,
        nullptr, nullptr, nullptr);
    cudaEventRecord(evJoin, s2);

    // 1) fused q & k projections (z: batch*2, odd -> k)   (stream 0)
    gemm_mma<0><<<dim3(CD / BN, TD / BM, BB * 2), NTHR, SMEM_BYTES>>>(
        xT, W + 0 * WW, q, bq, nullptr, CD, CD, CD, TC, 0, TC, CD,
        W + 1 * WW, k, bk);

    // 2) P = exp(scale * q.k^T), causal-masked, fp16 + partial row sums
    gemm_mma<3><<<dim3(TD / BN, TD / BM, BB), NTHR, SMEM_BYTES>>>(
        q, k, s, nullptr, nullptr, CD, CD, TD, TC, TC, SS, CD,
        nullptr, nullptr, nullptr);

    // 3) tiny reduce of partial sums (<=32 per row)
    k_rsreduce<<<(BB * TD) / 256, 256>>>();

    // join: PV needs vT
    cudaStreamWaitEvent(0, evJoin, 0);

    // 4) h = (P.vT^T)/rowsum, fp16 operands, fp32 accum
    gemm_mma<4><<<dim3(CD / BN, TD / BM, BB), NTHR, SMEM_BYTES>>>(
        s, vT, h, rs, nullptr, TD, TD, CD, SS, TC, TC, 0,
        nullptr, nullptr, nullptr);

    // 5) out = Wp.h^T + bp + x  (fp32 out)
    gemm_mma<2><<<dim3(TD / BN, CD / BM, BB), NTHR, SMEM_BYTES>>>(
        W + 3 * WW, h, out, bp, x, CD, CD, TD, 0, TC, TC, CD,
        nullptr, nullptr, nullptr);
}